// round 3
// baseline (speedup 1.0000x reference)
#include <cuda_runtime.h>
#include <math_constants.h>

// ---------------------------------------------------------------------------
// CasualAttention: out = softmax_causal((xWq)(xWk)^T / sqrt(d)) (xWv)
// B=4, S=2048, D_IN=D_OUT=1024, fp32 everywhere.
//
// Pipeline (4 launches, all graph-capturable, no allocations):
//   1) qkv_kernel    : one SGEMM M=8192, N=3072 (Wq|Wk|Wv), K=1024 -> g_q/g_k/g_v
//   2) scores_kernel : per-batch Q K^T * scale, lower-triangular tiles only
//   3) softmax_kernel: causal row softmax in-place (writes zeros above diag)
//   4) av_kernel     : P @ V with K-loop truncated at the causal bound
// ---------------------------------------------------------------------------

#define BM 128
#define BN 128
#define BK 16
#define TM 8
#define TN 8

static constexpr int Bb = 4;
static constexpr int S  = 2048;
static constexpr int D  = 1024;
static constexpr int M1 = Bb * S;   // 8192
static constexpr int N1 = 3 * D;    // 3072

// Scratch (allocation-free rule: __device__ globals)
__device__ float g_q[M1 * D];                       // 32 MB
__device__ float g_k[M1 * D];                       // 32 MB
__device__ float g_v[M1 * D];                       // 32 MB
__device__ float g_p[(size_t)Bb * S * S];           // 64 MB

// ---------------------------------------------------------------------------
// Kernel 1: fused QKV projection. C[8192, 3072] = X[8192,1024] @ [Wq|Wk|Wv]
// ---------------------------------------------------------------------------
__global__ __launch_bounds__(256) void qkv_kernel(
    const float* __restrict__ X,
    const float* __restrict__ Wq,
    const float* __restrict__ Wk,
    const float* __restrict__ Wv)
{
    __shared__ float As[BK][BM];
    __shared__ float Bs[BK][BN];

    const int n0 = blockIdx.x * BN;           // 0..3071, tile never straddles a W
    const int m0 = blockIdx.y * BM;
    const int which = n0 >> 10;
    const float* __restrict__ W = (which == 0) ? Wq : ((which == 1) ? Wk : Wv);
    float* __restrict__ Out     = (which == 0) ? g_q : ((which == 1) ? g_k : g_v);
    const int nW = n0 & (D - 1);              // column offset inside the chosen W

    const int t  = threadIdx.x;
    const int tx = t & 15;
    const int ty = t >> 4;

    float acc[TM][TN];
    #pragma unroll
    for (int i = 0; i < TM; i++)
        #pragma unroll
        for (int j = 0; j < TN; j++) acc[i][j] = 0.f;

    for (int k0 = 0; k0 < D; k0 += BK) {
        // A tile: As[kk][m] = X[m0+m][k0+kk]  (float4 along K, scatter into smem)
        #pragma unroll
        for (int it = 0; it < 2; it++) {
            int idx = t + it * 256;           // 0..511
            int m   = idx >> 2;
            int kq  = (idx & 3) * 4;
            float4 v = *(const float4*)(X + (size_t)(m0 + m) * D + k0 + kq);
            As[kq + 0][m] = v.x;
            As[kq + 1][m] = v.y;
            As[kq + 2][m] = v.z;
            As[kq + 3][m] = v.w;
        }
        // B tile: Bs[row][c] = W[k0+row][nW+c]  (float4 along N)
        #pragma unroll
        for (int it = 0; it < 2; it++) {
            int idx = t + it * 256;
            int row = idx >> 5;               // 0..15
            int c   = (idx & 31) * 4;
            *(float4*)&Bs[row][c] =
                *(const float4*)(W + (size_t)(k0 + row) * D + nW + c);
        }
        __syncthreads();

        #pragma unroll
        for (int kk = 0; kk < BK; kk++) {
            float a[TM], b[TN];
            #pragma unroll
            for (int i = 0; i < TM; i++) a[i] = As[kk][ty * TM + i];
            #pragma unroll
            for (int j = 0; j < TN; j++) b[j] = Bs[kk][tx * TN + j];
            #pragma unroll
            for (int i = 0; i < TM; i++)
                #pragma unroll
                for (int j = 0; j < TN; j++) acc[i][j] = fmaf(a[i], b[j], acc[i][j]);
        }
        __syncthreads();
    }

    #pragma unroll
    for (int i = 0; i < TM; i++) {
        const int gm = m0 + ty * TM + i;
        #pragma unroll
        for (int j = 0; j < TN; j += 4) {
            float4 v = make_float4(acc[i][j], acc[i][j + 1], acc[i][j + 2], acc[i][j + 3]);
            *(float4*)(Out + (size_t)gm * D + nW + tx * TN + j) = v;
        }
    }
}

// ---------------------------------------------------------------------------
// Kernel 2: per-batch scores = Q K^T * scale, lower-triangular tiles only.
// ---------------------------------------------------------------------------
__global__ __launch_bounds__(256) void scores_kernel()
{
    const int jt = blockIdx.x;                // key tile
    const int it = blockIdx.y;                // query tile
    if (jt > it) return;                      // strictly upper tiles: no work
    const int b  = blockIdx.z;

    const int i0 = it * BM;
    const int j0 = jt * BN;
    const float* __restrict__ Q  = g_q + (size_t)b * S * D;
    const float* __restrict__ Km = g_k + (size_t)b * S * D;
    float* __restrict__ P        = g_p + (size_t)b * S * S;

    __shared__ float As[BK][BM];
    __shared__ float Bs[BK][BN];

    const int t  = threadIdx.x;
    const int tx = t & 15;
    const int ty = t >> 4;

    float acc[TM][TN];
    #pragma unroll
    for (int i = 0; i < TM; i++)
        #pragma unroll
        for (int j = 0; j < TN; j++) acc[i][j] = 0.f;

    for (int k0 = 0; k0 < D; k0 += BK) {
        // Q tile (A-style transpose into smem)
        #pragma unroll
        for (int itL = 0; itL < 2; itL++) {
            int idx = t + itL * 256;
            int m   = idx >> 2;
            int kq  = (idx & 3) * 4;
            float4 v = *(const float4*)(Q + (size_t)(i0 + m) * D + k0 + kq);
            As[kq + 0][m] = v.x;
            As[kq + 1][m] = v.y;
            As[kq + 2][m] = v.z;
            As[kq + 3][m] = v.w;
        }
        // K tile (same orientation: rows are key positions, contiguous along k)
        #pragma unroll
        for (int itL = 0; itL < 2; itL++) {
            int idx = t + itL * 256;
            int n   = idx >> 2;
            int kq  = (idx & 3) * 4;
            float4 v = *(const float4*)(Km + (size_t)(j0 + n) * D + k0 + kq);
            Bs[kq + 0][n] = v.x;
            Bs[kq + 1][n] = v.y;
            Bs[kq + 2][n] = v.z;
            Bs[kq + 3][n] = v.w;
        }
        __syncthreads();

        #pragma unroll
        for (int kk = 0; kk < BK; kk++) {
            float a[TM], bvals[TN];
            #pragma unroll
            for (int i = 0; i < TM; i++) a[i] = As[kk][ty * TM + i];
            #pragma unroll
            for (int j = 0; j < TN; j++) bvals[j] = Bs[kk][tx * TN + j];
            #pragma unroll
            for (int i = 0; i < TM; i++)
                #pragma unroll
                for (int j = 0; j < TN; j++) acc[i][j] = fmaf(a[i], bvals[j], acc[i][j]);
        }
        __syncthreads();
    }

    const float scale = 0.03125f;             // 1/sqrt(1024)
    if (jt < it) {
        // full tile strictly below the diagonal: vectorized stores
        #pragma unroll
        for (int i = 0; i < TM; i++) {
            const int gi = i0 + ty * TM + i;
            #pragma unroll
            for (int j = 0; j < TN; j += 4) {
                float4 v = make_float4(acc[i][j] * scale, acc[i][j + 1] * scale,
                                       acc[i][j + 2] * scale, acc[i][j + 3] * scale);
                *(float4*)(P + (size_t)gi * S + j0 + tx * TN + j) = v;
            }
        }
    } else {
        // diagonal tile: predicated scalar stores (only j <= i)
        #pragma unroll
        for (int i = 0; i < TM; i++) {
            const int gi = i0 + ty * TM + i;
            #pragma unroll
            for (int j = 0; j < TN; j++) {
                const int gj = j0 + tx * TN + j;
                if (gj <= gi) P[(size_t)gi * S + gj] = acc[i][j] * scale;
            }
        }
    }
}

// ---------------------------------------------------------------------------
// Kernel 3: causal row softmax, in-place on g_p. Writes zeros for j > i so the
// AV GEMM can read full BK-blocks up to the causal bound.
// ---------------------------------------------------------------------------
__global__ __launch_bounds__(256) void softmax_kernel()
{
    const int r = blockIdx.x;                 // 0..8191 (b*S + i)
    const int i = r & (S - 1);
    float* __restrict__ row = g_p + (size_t)r * S;
    const int t = threadIdx.x;

    float v[8];
    float mx = -CUDART_INF_F;
    #pragma unroll
    for (int k = 0; k < 8; k++) {
        const int j = t + k * 256;
        v[k] = (j <= i) ? row[j] : -CUDART_INF_F;
        mx = fmaxf(mx, v[k]);
    }

    __shared__ float red[256];
    red[t] = mx;
    __syncthreads();
    #pragma unroll
    for (int s = 128; s > 0; s >>= 1) {
        if (t < s) red[t] = fmaxf(red[t], red[t + s]);
        __syncthreads();
    }
    mx = red[0];
    __syncthreads();

    float sum = 0.f;
    #pragma unroll
    for (int k = 0; k < 8; k++) {
        v[k] = __expf(v[k] - mx);             // exp(-inf) -> 0 for masked j
        sum += v[k];
    }
    red[t] = sum;
    __syncthreads();
    #pragma unroll
    for (int s = 128; s > 0; s >>= 1) {
        if (t < s) red[t] += red[t + s];
        __syncthreads();
    }
    const float inv = 1.0f / red[0];

    #pragma unroll
    for (int k = 0; k < 8; k++) {
        const int j = t + k * 256;
        row[j] = v[k] * inv;                  // zeros above the diagonal
    }
}

// ---------------------------------------------------------------------------
// Kernel 4: out = P @ V per batch; K-loop truncated at the causal bound.
// ---------------------------------------------------------------------------
__global__ __launch_bounds__(256) void av_kernel(float* __restrict__ OutAll)
{
    const int nt = blockIdx.x;
    const int mt = blockIdx.y;
    const int b  = blockIdx.z;
    const int m0 = mt * BM;
    const int n0 = nt * BN;

    const float* __restrict__ P = g_p + (size_t)b * S * S;
    const float* __restrict__ V = g_v + (size_t)b * S * D;
    float* __restrict__ O       = OutAll + (size_t)b * S * D;

    __shared__ float As[BK][BM];
    __shared__ float Bs[BK][BN];

    const int t  = threadIdx.x;
    const int tx = t & 15;
    const int ty = t >> 4;

    float acc[TM][TN];
    #pragma unroll
    for (int i = 0; i < TM; i++)
        #pragma unroll
        for (int j = 0; j < TN; j++) acc[i][j] = 0.f;

    const int kmax = m0 + BM;                 // probs are zero beyond the diagonal
    for (int k0 = 0; k0 < kmax; k0 += BK) {
        // P tile: As[kk][m] = P[m0+m][k0+kk] (row stride S)
        #pragma unroll
        for (int itL = 0; itL < 2; itL++) {
            int idx = t + itL * 256;
            int m   = idx >> 2;
            int kq  = (idx & 3) * 4;
            float4 v = *(const float4*)(P + (size_t)(m0 + m) * S + k0 + kq);
            As[kq + 0][m] = v.x;
            As[kq + 1][m] = v.y;
            As[kq + 2][m] = v.z;
            As[kq + 3][m] = v.w;
        }
        // V tile: Bs[row][c] = V[k0+row][n0+c]
        #pragma unroll
        for (int itL = 0; itL < 2; itL++) {
            int idx = t + itL * 256;
            int row = idx >> 5;
            int c   = (idx & 31) * 4;
            *(float4*)&Bs[row][c] =
                *(const float4*)(V + (size_t)(k0 + row) * D + n0 + c);
        }
        __syncthreads();

        #pragma unroll
        for (int kk = 0; kk < BK; kk++) {
            float a[TM], bvals[TN];
            #pragma unroll
            for (int i = 0; i < TM; i++) a[i] = As[kk][ty * TM + i];
            #pragma unroll
            for (int j = 0; j < TN; j++) bvals[j] = Bs[kk][tx * TN + j];
            #pragma unroll
            for (int i = 0; i < TM; i++)
                #pragma unroll
                for (int j = 0; j < TN; j++) acc[i][j] = fmaf(a[i], bvals[j], acc[i][j]);
        }
        __syncthreads();
    }

    #pragma unroll
    for (int i = 0; i < TM; i++) {
        const int gm = m0 + ty * TM + i;
        #pragma unroll
        for (int j = 0; j < TN; j += 4) {
            float4 v = make_float4(acc[i][j], acc[i][j + 1], acc[i][j + 2], acc[i][j + 3]);
            *(float4*)(O + (size_t)gm * D + n0 + tx * TN + j) = v;
        }
    }
}

// ---------------------------------------------------------------------------
// kernel_launch: inputs in metadata order (x, Wq, Wk, Wv); output fp32
// [4, 2048, 1024]. Pure kernel launches — graph-capturable, allocation-free.
// ---------------------------------------------------------------------------
extern "C" void kernel_launch(void* const* d_in, const int* in_sizes, int n_in,
                              void* d_out, int out_size)
{
    const float* x  = (const float*)d_in[0];
    const float* Wq = (const float*)d_in[1];
    const float* Wk = (const float*)d_in[2];
    const float* Wv = (const float*)d_in[3];
    float* out      = (float*)d_out;

    qkv_kernel<<<dim3(N1 / BN, M1 / BM), 256>>>(x, Wq, Wk, Wv);
    scores_kernel<<<dim3(S / BN, S / BM, Bb), 256>>>();
    softmax_kernel<<<Bb * S, 256>>>();
    av_kernel<<<dim3(D / BN, S / BM, Bb), 256>>>(out);
}